// round 16
// baseline (speedup 1.0000x reference)
#include <cuda_runtime.h>
#include <cuda_bf16.h>
#include <cstdint>

#define NEXP 64
#define KDIM 1024
#define NROWS 131072
#define HIGH_NEG -100000.0f
#define CRANK0 98303u

// ---------------- scratch ----------------
#define NBINS 8192
#define CAP 8192
__device__ uint32_t g_hist1[NEXP * NBINS];
__device__ uint32_t g_cand[NEXP * CAP];
__device__ uint32_t g_cnt[NEXP];
__device__ uint32_t g_bkt0[NEXP], g_rnk0[NEXP];
__device__ float    g_blo[NEXP], g_bhi[NEXP];
__device__ float    g_tcol[NEXP];
__device__ __nv_bfloat16 g_whi[NEXP * KDIM];
__device__ __nv_bfloat16 g_wlo[NEXP * KDIM];
__device__ uint32_t g_done_fb;
__device__ uint32_t g_done_sel;

// ---------------- helpers ----------------
__device__ __forceinline__ uint32_t f2o(float f) {
    uint32_t u = __float_as_uint(f);
    return u ^ ((u & 0x80000000u) ? 0xFFFFFFFFu : 0x80000000u);
}
__device__ __forceinline__ float o2f(uint32_t u) {
    u ^= ((u & 0x80000000u) ? 0x80000000u : 0xFFFFFFFFu);
    return __uint_as_float(u);
}
__device__ __forceinline__ uint32_t smem_u32(const void* p) {
    uint32_t a;
    asm("{ .reg .u64 t; cvta.to.shared.u64 t, %1; cvt.u32.u64 %0, t; }" : "=r"(a) : "l"(p));
    return a;
}
__device__ __forceinline__ void ldmx4(uint32_t* r, uint32_t addr) {
    asm volatile("ldmatrix.sync.aligned.m8n8.x4.shared.b16 {%0,%1,%2,%3}, [%4];"
                 : "=r"(r[0]), "=r"(r[1]), "=r"(r[2]), "=r"(r[3]) : "r"(addr));
}
__device__ __forceinline__ void mma_bf16(float* d, const uint32_t* a,
                                         uint32_t b0, uint32_t b1) {
    asm volatile(
        "mma.sync.aligned.m16n8k16.row.col.f32.bf16.bf16.f32 "
        "{%0,%1,%2,%3}, {%4,%5,%6,%7}, {%8,%9}, {%0,%1,%2,%3};"
        : "+f"(d[0]), "+f"(d[1]), "+f"(d[2]), "+f"(d[3])
        : "r"(a[0]), "r"(a[1]), "r"(a[2]), "r"(a[3]), "r"(b0), "r"(b1));
}
__device__ __forceinline__ void cpasync16(uint32_t dst, const void* src) {
    asm volatile("cp.async.cg.shared.global [%0], [%1], 16;"
                 :: "r"(dst), "l"(src) : "memory");
}
__device__ __forceinline__ uint32_t warp_iscan(uint32_t v, int lane) {
#pragma unroll
    for (int o = 1; o < 32; o <<= 1) {
        uint32_t t = __shfl_up_sync(0xffffffffu, v, o);
        if (lane >= o) v += t;
    }
    return v;
}
__device__ __forceinline__ void spin_until(uint32_t* flag, uint32_t target) {
    uint32_t d;
    while (true) {
        asm volatile("ld.global.acquire.gpu.u32 %0, [%1];" : "=r"(d) : "l"(flag));
        if (d >= target) break;
        __nanosleep(64);
    }
}
#define BAR_SYNC(id, n)   asm volatile("bar.sync %0, %1;"   :: "r"(id), "r"(n) : "memory")
#define BAR_ARRIVE(id, n) asm volatile("bar.arrive %0, %1;" :: "r"(id), "r"(n) : "memory")

// ---------------- launch idx 0: fused setup ----------------
__global__ void setup(const float* __restrict__ W) {
    int i = blockIdx.x * blockDim.x + threadIdx.x;   // 131072 threads
    reinterpret_cast<uint4*>(g_hist1)[i] = make_uint4(0u, 0u, 0u, 0u);
    if (i < NEXP * KDIM) {
        float v = W[i];
        __nv_bfloat16 h = __float2bfloat16(v);
        g_whi[i] = h;
        g_wlo[i] = __float2bfloat16(v - __bfloat162float(h));
    }
    if (i < NEXP) g_cnt[i] = 0u;
    if (i == 0) { g_done_fb = 0u; g_done_sel = 0u; }
}

// ---------------- launch idx 1: warp-specialized mma GEMM (R14 exact) --------
#define BM 128
#define CHUNK 64
#define NCH (KDIM / CHUNK)
#define SM_A(st)  ((st) * 32768)
#define SM_B(st)  (65536 + (st) * 16384)
#define SMEM_TOTAL 98304
#define STG 68
#define BAR_FULL0 1
#define BAR_FREE0 3
#define BAR_CONS  5
#define BAR_STG   6

__global__ __launch_bounds__(256, 2) void gemm_ws(
    const float* __restrict__ x, const float* __restrict__ bias,
    const float* __restrict__ noise, float* __restrict__ out)
{
    extern __shared__ char smem[];
    const uint32_t sb = smem_u32(smem);
    const int tid = threadIdx.x;
    const int wid = tid >> 5, lid = tid & 31;
    const int rowBase = blockIdx.x * BM;
    const float* xr = x + (size_t)rowBase * KDIM;

    if (wid >= 4) {
        // ================= PRODUCERS =================
        const int pt = tid - 128;
        float4 xb[16];
        auto loadX = [&](int kc) {
#pragma unroll
            for (int i = 0; i < 16; i++) {
                int l = pt + i * 128;
                int r = l >> 4, q = l & 15;
                xb[i] = *reinterpret_cast<const float4*>(xr + (size_t)r * KDIM + kc + q * 4);
            }
        };
        auto storeA = [&](int st) {
#pragma unroll
            for (int i = 0; i < 16; i++) {
                int l = pt + i * 128;
                int r = l >> 4, q = l & 15;
                float4 v = xb[i];
                uint32_t h01, h23, l01, l23;
                asm("cvt.rn.bf16x2.f32 %0, %1, %2;" : "=r"(h01) : "f"(v.y), "f"(v.x));
                asm("cvt.rn.bf16x2.f32 %0, %1, %2;" : "=r"(h23) : "f"(v.w), "f"(v.z));
                float r0 = v.x - __uint_as_float(h01 << 16);
                float r1 = v.y - __uint_as_float(h01 & 0xFFFF0000u);
                float r2 = v.z - __uint_as_float(h23 << 16);
                float r3 = v.w - __uint_as_float(h23 & 0xFFFF0000u);
                asm("cvt.rn.bf16x2.f32 %0, %1, %2;" : "=r"(l01) : "f"(r1), "f"(r0));
                asm("cvt.rn.bf16x2.f32 %0, %1, %2;" : "=r"(l23) : "f"(r3), "f"(r2));
                uint32_t off = (uint32_t)(r * 128) +
                               (((uint32_t)(q * 8)) ^ ((uint32_t)((r & 7) << 4)));
                *reinterpret_cast<uint2*>(smem + SM_A(st) + off) = make_uint2(h01, h23);
                *reinterpret_cast<uint2*>(smem + SM_A(st) + 16384 + off) = make_uint2(l01, l23);
            }
        };
        auto issueB = [&](int kc, int st) {
            const char* whp = reinterpret_cast<const char*>(g_whi);
            const char* wlp = reinterpret_cast<const char*>(g_wlo);
#pragma unroll
            for (int i = 0; i < 4; i++) {
                int l = pt + i * 128;
                int e = l >> 3, q = l & 7;
                uint32_t off = (uint32_t)(e * 128) +
                               (((uint32_t)(q * 16)) ^ ((uint32_t)((e & 7) << 4)));
                size_t src = (size_t)(e * KDIM + kc) * 2 + q * 16;
                cpasync16(sb + SM_B(st) + off, whp + src);
                cpasync16(sb + SM_B(st) + 8192 + off, wlp + src);
            }
            asm volatile("cp.async.commit_group;" ::: "memory");
        };

        loadX(0);
        for (int c = 0; c < NCH; c++) {
            const int st = c & 1;
            if (c >= 2) BAR_SYNC(BAR_FREE0 + st, 256);
            issueB(c * CHUNK, st);
            storeA(st);
            if (c + 1 < NCH) loadX((c + 1) * CHUNK);
            asm volatile("cp.async.wait_group 0;" ::: "memory");
            BAR_ARRIVE(BAR_FULL0 + st, 256);
        }
        BAR_SYNC(BAR_STG, 256);
    } else {
        // ================= CONSUMERS =================
        float acc[2][2][4][4];
#pragma unroll
        for (int g2 = 0; g2 < 2; g2++)
#pragma unroll
            for (int mi = 0; mi < 2; mi++)
#pragma unroll
                for (int ni = 0; ni < 4; ni++)
#pragma unroll
                    for (int j = 0; j < 4; j++) acc[g2][mi][ni][j] = 0.0f;

        const uint32_t amask = (uint32_t)((lid & 7) << 4);
        const uint32_t asel = (uint32_t)((lid >> 4) * 16);
        const uint32_t aRowOff = (uint32_t)(wid * 32 + (lid & 15)) * 128;
        const uint32_t bsel = (uint32_t)(((lid >> 3) & 1) * 16);
        const uint32_t bRow0 = (uint32_t)(((lid >> 4) << 3) + (lid & 7));

        for (int c = 0; c < NCH; c++) {
            const int st = c & 1;
            BAR_SYNC(BAR_FULL0 + st, 256);
            const uint32_t aHi = sb + (uint32_t)SM_A(st) + aRowOff;
            const uint32_t aLo = aHi + 16384;
            const uint32_t bHi = sb + (uint32_t)SM_B(st);
#pragma unroll
            for (int kk = 0; kk < 4; kk++) {
                const uint32_t ca = (asel + (uint32_t)(kk * 32)) ^ amask;
                const uint32_t cb = (bsel + (uint32_t)(kk * 32)) ^ amask;
                uint32_t ah[2][4], al[2][4];
#pragma unroll
                for (int mi = 0; mi < 2; mi++) {
                    ldmx4(ah[mi], aHi + (uint32_t)(mi * 2048) + ca);
                    ldmx4(al[mi], aLo + (uint32_t)(mi * 2048) + ca);
                }
#pragma unroll
                for (int g2 = 0; g2 < 2; g2++) {
                    const uint32_t bb = bHi + (uint32_t)(g2 * 32 * 128);
                    uint32_t bh[8], bl[8];
                    ldmx4(bh,     bb + bRow0 * 128 + cb);
                    ldmx4(bh + 4, bb + (bRow0 + 16) * 128 + cb);
                    ldmx4(bl,     bb + 8192 + bRow0 * 128 + cb);
                    ldmx4(bl + 4, bb + 8192 + (bRow0 + 16) * 128 + cb);
#pragma unroll
                    for (int mi = 0; mi < 2; mi++)
#pragma unroll
                        for (int ni = 0; ni < 4; ni++)
                            mma_bf16(acc[g2][mi][ni], ah[mi], bh[ni * 2], bh[ni * 2 + 1]);
#pragma unroll
                    for (int mi = 0; mi < 2; mi++)
#pragma unroll
                        for (int ni = 0; ni < 4; ni++)
                            mma_bf16(acc[g2][mi][ni], ah[mi], bl[ni * 2], bl[ni * 2 + 1]);
#pragma unroll
                    for (int mi = 0; mi < 2; mi++)
#pragma unroll
                        for (int ni = 0; ni < 4; ni++)
                            mma_bf16(acc[g2][mi][ni], al[mi], bh[ni * 2], bh[ni * 2 + 1]);
                }
            }
            BAR_ARRIVE(BAR_FREE0 + st, 256);
        }
        BAR_SYNC(BAR_CONS, 128);
        float* stg = reinterpret_cast<float*>(smem);
#pragma unroll
        for (int g2 = 0; g2 < 2; g2++)
#pragma unroll
            for (int mi = 0; mi < 2; mi++) {
                int row = wid * 32 + mi * 16 + (lid >> 2);
#pragma unroll
                for (int ni = 0; ni < 4; ni++) {
                    int col = g2 * 32 + ni * 8 + 2 * (lid & 3);
                    *reinterpret_cast<float2*>(&stg[row * STG + col]) =
                        make_float2(acc[g2][mi][ni][0], acc[g2][mi][ni][1]);
                    *reinterpret_cast<float2*>(&stg[(row + 8) * STG + col]) =
                        make_float2(acc[g2][mi][ni][2], acc[g2][mi][ni][3]);
                }
            }
        BAR_SYNC(BAR_STG, 256);
    }

    // ---- all 256 threads: coalesced write + fused 13-bit hist1 ----
    float* stg = reinterpret_cast<float*>(smem);
    const float* nz = noise + (size_t)rowBase * NEXP;
    float* op = out + (size_t)rowBase * NEXP;
#pragma unroll
    for (int j = 0; j < 8; j++) {
        int l = tid + j * 256;
        int r = l >> 4, q = (l & 15) * 4;
        float4 nv = *reinterpret_cast<const float4*>(nz + r * NEXP + q);
        float4 bv = *reinterpret_cast<const float4*>(bias + q);
        float4 o;
        o.x = (stg[r * STG + q + 0] + bv.x) + 0.1f * nv.x;
        o.y = (stg[r * STG + q + 1] + bv.y) + 0.1f * nv.y;
        o.z = (stg[r * STG + q + 2] + bv.z) + 0.1f * nv.z;
        o.w = (stg[r * STG + q + 3] + bv.w) + 0.1f * nv.w;
        *reinterpret_cast<float4*>(op + r * NEXP + q) = o;
        atomicAdd(&g_hist1[((q + 0) << 13) | (f2o(o.x) >> 19)], 1u);
        atomicAdd(&g_hist1[((q + 1) << 13) | (f2o(o.y) >> 19)], 1u);
        atomicAdd(&g_hist1[((q + 2) << 13) | (f2o(o.z) >> 19)], 1u);
        atomicAdd(&g_hist1[((q + 3) << 13) | (f2o(o.w) >> 19)], 1u);
    }
}

// ---------------- launch idx 2: fused find_buckets + collect -----------------
// Single-rank (t = s0 exact-mask theorem); float-interval fast path + exact confirm.
__global__ __launch_bounds__(256) void fb_collect(const float4* __restrict__ lg, int n4) {
    __shared__ uint32_t sh[NBINS];
    __shared__ uint32_t wsum[8], woff[8];
    __shared__ uint32_t rbin, rrnk;
    const int tid = threadIdx.x, lane = tid & 31, w = tid >> 5;

    if (blockIdx.x < NEXP) {
        const int e = blockIdx.x;
        const uint32_t* h = &g_hist1[e << 13];
        for (int i = tid; i < NBINS; i += 256) sh[i] = h[i];
        __syncthreads();
        uint32_t bins[32];
        uint32_t s = 0;
#pragma unroll
        for (int j = 0; j < 32; j++) { bins[j] = sh[tid * 32 + j]; s += bins[j]; }
        uint32_t ps = warp_iscan(s, lane);
        if (lane == 31) wsum[w] = ps;
        __syncthreads();
        if (tid == 0) {
            uint32_t r2 = 0;
            for (int i = 0; i < 8; i++) { woff[i] = r2; r2 += wsum[i]; }
        }
        __syncthreads();
        uint32_t base = woff[w] + ps - s;
        if (base <= CRANK0 && CRANK0 < base + s) {
            uint32_t cum = base;
#pragma unroll
            for (int j = 0; j < 32; j++) {
                if (CRANK0 < cum + bins[j]) { rbin = (uint32_t)(tid * 32 + j); rrnk = CRANK0 - cum; break; }
                cum += bins[j];
            }
        }
        __syncthreads();
        if (tid == 0) {
            g_bkt0[e] = rbin; g_rnk0[e] = rrnk;
            g_blo[e] = o2f(rbin << 19);
            g_bhi[e] = o2f((rbin << 19) | 0x7FFFFu);
            __threadfence();
            atomicAdd(&g_done_fb, 1u);
        }
    }

    if (tid == 0) spin_until(&g_done_fb, NEXP);
    __syncthreads();

    // register-resident buckets + float interval bounds (4 fixed columns/thread)
    const int c0 = (tid * 4) & 63;
    uint32_t b0r[4];
    float lo[4], hi[4];
#pragma unroll
    for (int j = 0; j < 4; j++) {
        b0r[j] = g_bkt0[c0 + j];
        lo[j] = g_blo[c0 + j];
        hi[j] = g_bhi[c0 + j];
    }

    for (int i = blockIdx.x * 256 + tid; i < n4; i += gridDim.x * 256) {
        float4 v = lg[i];
        float vals[4] = {v.x, v.y, v.z, v.w};
#pragma unroll
        for (int j = 0; j < 4; j++) {
            float f = vals[j];
            if (f >= lo[j] && f <= hi[j]) {
                uint32_t u = f2o(f);               // exact confirm (handles +-0 straddle)
                if ((u >> 19) == b0r[j]) {
                    uint32_t pos = atomicAdd(&g_cnt[c0 + j], 1u);
                    if (pos < CAP) g_cand[((c0 + j) << 13) | pos] = u;
                }
            }
        }
    }
}

// ---------------- launch idx 3: fused select + thread-per-row masks/softmax --
__global__ __launch_bounds__(256) void sel_row(float* __restrict__ lg) {
    __shared__ uint32_t hist[4096];
    __shared__ uint32_t wsum[8], woff[8];
    __shared__ uint32_t tb, bb;
    __shared__ uint32_t mbuf[64];
    __shared__ uint32_t mcnt;
    __shared__ __align__(16) float tc[NEXP];
    const int tid = threadIdx.x, lane = tid & 31, w = tid >> 5;

    if (blockIdx.x < NEXP) {
        // ---- select rank-98303 value exactly (single rank) ----
        const int e = blockIdx.x;
        const uint32_t* cand = &g_cand[e << 13];
        int n = (int)g_cnt[e]; if (n > CAP) n = CAP;
        const uint32_t r = g_rnk0[e];
#pragma unroll
        for (int j = 0; j < 16; j++) hist[tid * 16 + j] = 0u;
        __syncthreads();
        for (int i = tid; i < n; i += 256) atomicAdd(&hist[(cand[i] >> 7) & 0xFFFu], 1u);
        __syncthreads();
        uint32_t loc[16];
        uint32_t s = 0;
#pragma unroll
        for (int j = 0; j < 16; j++) { loc[j] = hist[tid * 16 + j]; s += loc[j]; }
        uint32_t ps = warp_iscan(s, lane);
        if (lane == 31) wsum[w] = ps;
        __syncthreads();
        if (tid == 0) {
            uint32_t r2 = 0;
            for (int i = 0; i < 8; i++) { woff[i] = r2; r2 += wsum[i]; }
            mcnt = 0u;
        }
        __syncthreads();
        uint32_t base = woff[w] + ps - s;
        if (base <= r && r < base + s) {
            uint32_t cum = base;
#pragma unroll
            for (int j = 0; j < 16; j++) {
                if (r < cum + loc[j]) { tb = (uint32_t)(tid * 16 + j); bb = cum; break; }
                cum += loc[j];
            }
        }
        __syncthreads();
        for (int i = tid; i < n; i += 256) {
            uint32_t u = cand[i];
            if (((u >> 7) & 0xFFFu) == tb) {
                uint32_t k = atomicAdd(&mcnt, 1u);
                if (k < 64) mbuf[k] = u;
            }
        }
        __syncthreads();
        if (tid == 0) {
            int m = (int)mcnt; if (m > 64) m = 64;
            for (int i2 = 1; i2 < m; i2++) {
                uint32_t key = mbuf[i2];
                int j2 = i2 - 1;
                while (j2 >= 0 && mbuf[j2] > key) { mbuf[j2 + 1] = mbuf[j2]; j2--; }
                mbuf[j2 + 1] = key;
            }
            g_tcol[e] = o2f(mbuf[r - bb]);    // t = s0 (exact mask)
            __threadfence();
            atomicAdd(&g_done_sel, 1u);
        }
    }

    if (tid == 0) spin_until(&g_done_sel, NEXP);
    __syncthreads();
    if (tid < NEXP) tc[tid] = g_tcol[tid];
    __syncthreads();

    // ---- thread-per-row: capacity mask + top-3 + softmax (branchless scan) ----
    const int row = blockIdx.x * 256 + tid;
    const float4* rp = reinterpret_cast<const float4*>(lg + (size_t)row * NEXP);
    const float4* t4 = reinterpret_cast<const float4*>(tc);

    float a = HIGH_NEG, b = HIGH_NEG, c = -3.402823466e38f;
    int ia = 0, ib = 0;
#define PROC(vv, tt, col) do {                                        \
        float m = (vv > tt) ? vv : HIGH_NEG;                          \
        bool ga = m > a, gb = m > b, gc = m > c;                      \
        float nc = gb ? b : (gc ? m : c);                             \
        int  nib = ga ? ia : (gb ? (col) : ib);                       \
        float nb = ga ? a : (gb ? m : b);                             \
        int  nia = ga ? (col) : ia;                                   \
        float na = ga ? m : a;                                        \
        a = na; b = nb; c = nc; ia = nia; ib = nib;                   \
    } while (0)

#pragma unroll
    for (int j = 0; j < 16; j++) {
        float4 v = rp[j];
        float4 t = t4[j];
        PROC(v.x, t.x, j * 4 + 0);
        PROC(v.y, t.y, j * 4 + 1);
        PROC(v.z, t.z, j * 4 + 2);
        PROC(v.w, t.w, j * 4 + 3);
    }
#undef PROC

    float* op = lg + (size_t)row * NEXP;
    float4* op4 = reinterpret_cast<float4*>(op);
    if (a > c) {
        // survivors: a always; b iff b > c  (thr = c, exact)
        bool keepb = (b > c);
        float e1;
        asm("ex2.approx.f32 %0, %1;" : "=f"(e1) : "f"((b - a) * 1.4426950408889634f));
        e1 = keepb ? e1 : 0.0f;
        float inv;
        asm("rcp.approx.f32 %0, %1;" : "=f"(inv) : "f"(1.0f + e1));
        float4 z = make_float4(0.0f, 0.0f, 0.0f, 0.0f);
#pragma unroll
        for (int j = 0; j < 16; j++) op4[j] = z;
        op[ia] = inv;                      // e0 = 1 -> e0*inv = inv
        if (keepb) op[ib] = e1 * inv;
    } else {
        // zero survivors -> reference softmax over all-equal HIGH_NEG = uniform
        float4 u = make_float4(0.015625f, 0.015625f, 0.015625f, 0.015625f);
#pragma unroll
        for (int j = 0; j < 16; j++) op4[j] = u;
    }
}

// ---------------- launch ----------------
extern "C" void kernel_launch(void* const* d_in, const int* in_sizes, int n_in,
                              void* d_out, int out_size) {
    const float *x = nullptr, *noise = nullptr, *W = nullptr, *bias = nullptr;
    for (int i = 0; i < n_in; i++) {
        switch (in_sizes[i]) {
            case NROWS * KDIM: x     = (const float*)d_in[i]; break;
            case NROWS * NEXP: noise = (const float*)d_in[i]; break;
            case NEXP * KDIM:  W     = (const float*)d_in[i]; break;
            case NEXP:         bias  = (const float*)d_in[i]; break;
            default: break;
        }
    }
    float* out = (float*)d_out;
    const int n4 = NROWS * NEXP / 4;

    cudaFuncSetAttribute(gemm_ws, cudaFuncAttributeMaxDynamicSharedMemorySize, SMEM_TOTAL);

    setup<<<512, 256>>>(W);                                          // idx 0
    gemm_ws<<<NROWS / BM, 256, SMEM_TOTAL>>>(x, bias, noise, out);   // idx 1
    fb_collect<<<4096, 256>>>((const float4*)out, n4);               // idx 2
    sel_row<<<NROWS / 256, 256>>>(out);                              // idx 3
}

// round 17
// speedup vs baseline: 1.0433x; 1.0433x over previous
#include <cuda_runtime.h>
#include <cuda_bf16.h>
#include <cstdint>

#define NEXP 64
#define KDIM 1024
#define NROWS 131072
#define HIGH_NEG -100000.0f
#define CRANK0 98303u

// ---------------- scratch ----------------
#define NBINS 8192
#define CAP 8192
__device__ uint32_t g_hist1[NEXP * NBINS];
__device__ uint32_t g_cand[NEXP * CAP];
__device__ uint32_t g_cnt[NEXP];
__device__ uint32_t g_bkt0[NEXP], g_rnk0[NEXP];
__device__ float    g_blo[NEXP], g_bhi[NEXP];
__device__ float    g_tcol[NEXP];
__device__ __nv_bfloat16 g_whi[NEXP * KDIM];
__device__ __nv_bfloat16 g_wlo[NEXP * KDIM];

// ---------------- helpers ----------------
__device__ __forceinline__ uint32_t f2o(float f) {
    uint32_t u = __float_as_uint(f);
    return u ^ ((u & 0x80000000u) ? 0xFFFFFFFFu : 0x80000000u);
}
__device__ __forceinline__ float o2f(uint32_t u) {
    u ^= ((u & 0x80000000u) ? 0x80000000u : 0xFFFFFFFFu);
    return __uint_as_float(u);
}
__device__ __forceinline__ uint32_t smem_u32(const void* p) {
    uint32_t a;
    asm("{ .reg .u64 t; cvta.to.shared.u64 t, %1; cvt.u32.u64 %0, t; }" : "=r"(a) : "l"(p));
    return a;
}
__device__ __forceinline__ void ldmx4(uint32_t* r, uint32_t addr) {
    asm volatile("ldmatrix.sync.aligned.m8n8.x4.shared.b16 {%0,%1,%2,%3}, [%4];"
                 : "=r"(r[0]), "=r"(r[1]), "=r"(r[2]), "=r"(r[3]) : "r"(addr));
}
__device__ __forceinline__ void mma_bf16(float* d, const uint32_t* a,
                                         uint32_t b0, uint32_t b1) {
    asm volatile(
        "mma.sync.aligned.m16n8k16.row.col.f32.bf16.bf16.f32 "
        "{%0,%1,%2,%3}, {%4,%5,%6,%7}, {%8,%9}, {%0,%1,%2,%3};"
        : "+f"(d[0]), "+f"(d[1]), "+f"(d[2]), "+f"(d[3])
        : "r"(a[0]), "r"(a[1]), "r"(a[2]), "r"(a[3]), "r"(b0), "r"(b1));
}
__device__ __forceinline__ void cpasync16(uint32_t dst, const void* src) {
    asm volatile("cp.async.cg.shared.global [%0], [%1], 16;"
                 :: "r"(dst), "l"(src) : "memory");
}
__device__ __forceinline__ uint32_t warp_iscan(uint32_t v, int lane) {
#pragma unroll
    for (int o = 1; o < 32; o <<= 1) {
        uint32_t t = __shfl_up_sync(0xffffffffu, v, o);
        if (lane >= o) v += t;
    }
    return v;
}
#define BAR_SYNC(id, n)   asm volatile("bar.sync %0, %1;"   :: "r"(id), "r"(n) : "memory")
#define BAR_ARRIVE(id, n) asm volatile("bar.arrive %0, %1;" :: "r"(id), "r"(n) : "memory")

// ---------------- launch idx 0: fused setup ----------------
__global__ void setup(const float* __restrict__ W) {
    int i = blockIdx.x * blockDim.x + threadIdx.x;   // 131072 threads
    reinterpret_cast<uint4*>(g_hist1)[i] = make_uint4(0u, 0u, 0u, 0u);
    if (i < NEXP * KDIM) {
        float v = W[i];
        __nv_bfloat16 h = __float2bfloat16(v);
        g_whi[i] = h;
        g_wlo[i] = __float2bfloat16(v - __bfloat162float(h));
    }
    if (i < NEXP) g_cnt[i] = 0u;
}

// ---------------- launch idx 1: warp-specialized mma GEMM (R14 exact) --------
#define BM 128
#define CHUNK 64
#define NCH (KDIM / CHUNK)
#define SM_A(st)  ((st) * 32768)
#define SM_B(st)  (65536 + (st) * 16384)
#define SMEM_TOTAL 98304
#define STG 68
#define BAR_FULL0 1
#define BAR_FREE0 3
#define BAR_CONS  5
#define BAR_STG   6

__global__ __launch_bounds__(256, 2) void gemm_ws(
    const float* __restrict__ x, const float* __restrict__ bias,
    const float* __restrict__ noise, float* __restrict__ out)
{
    extern __shared__ char smem[];
    const uint32_t sb = smem_u32(smem);
    const int tid = threadIdx.x;
    const int wid = tid >> 5, lid = tid & 31;
    const int rowBase = blockIdx.x * BM;
    const float* xr = x + (size_t)rowBase * KDIM;

    if (wid >= 4) {
        // ================= PRODUCERS =================
        const int pt = tid - 128;
        float4 xb[16];
        auto loadX = [&](int kc) {
#pragma unroll
            for (int i = 0; i < 16; i++) {
                int l = pt + i * 128;
                int r = l >> 4, q = l & 15;
                xb[i] = *reinterpret_cast<const float4*>(xr + (size_t)r * KDIM + kc + q * 4);
            }
        };
        auto storeA = [&](int st) {
#pragma unroll
            for (int i = 0; i < 16; i++) {
                int l = pt + i * 128;
                int r = l >> 4, q = l & 15;
                float4 v = xb[i];
                uint32_t h01, h23, l01, l23;
                asm("cvt.rn.bf16x2.f32 %0, %1, %2;" : "=r"(h01) : "f"(v.y), "f"(v.x));
                asm("cvt.rn.bf16x2.f32 %0, %1, %2;" : "=r"(h23) : "f"(v.w), "f"(v.z));
                float r0 = v.x - __uint_as_float(h01 << 16);
                float r1 = v.y - __uint_as_float(h01 & 0xFFFF0000u);
                float r2 = v.z - __uint_as_float(h23 << 16);
                float r3 = v.w - __uint_as_float(h23 & 0xFFFF0000u);
                asm("cvt.rn.bf16x2.f32 %0, %1, %2;" : "=r"(l01) : "f"(r1), "f"(r0));
                asm("cvt.rn.bf16x2.f32 %0, %1, %2;" : "=r"(l23) : "f"(r3), "f"(r2));
                uint32_t off = (uint32_t)(r * 128) +
                               (((uint32_t)(q * 8)) ^ ((uint32_t)((r & 7) << 4)));
                *reinterpret_cast<uint2*>(smem + SM_A(st) + off) = make_uint2(h01, h23);
                *reinterpret_cast<uint2*>(smem + SM_A(st) + 16384 + off) = make_uint2(l01, l23);
            }
        };
        auto issueB = [&](int kc, int st) {
            const char* whp = reinterpret_cast<const char*>(g_whi);
            const char* wlp = reinterpret_cast<const char*>(g_wlo);
#pragma unroll
            for (int i = 0; i < 4; i++) {
                int l = pt + i * 128;
                int e = l >> 3, q = l & 7;
                uint32_t off = (uint32_t)(e * 128) +
                               (((uint32_t)(q * 16)) ^ ((uint32_t)((e & 7) << 4)));
                size_t src = (size_t)(e * KDIM + kc) * 2 + q * 16;
                cpasync16(sb + SM_B(st) + off, whp + src);
                cpasync16(sb + SM_B(st) + 8192 + off, wlp + src);
            }
            asm volatile("cp.async.commit_group;" ::: "memory");
        };

        loadX(0);
        for (int c = 0; c < NCH; c++) {
            const int st = c & 1;
            if (c >= 2) BAR_SYNC(BAR_FREE0 + st, 256);
            issueB(c * CHUNK, st);
            storeA(st);
            if (c + 1 < NCH) loadX((c + 1) * CHUNK);
            asm volatile("cp.async.wait_group 0;" ::: "memory");
            BAR_ARRIVE(BAR_FULL0 + st, 256);
        }
        BAR_SYNC(BAR_STG, 256);
    } else {
        // ================= CONSUMERS =================
        float acc[2][2][4][4];
#pragma unroll
        for (int g2 = 0; g2 < 2; g2++)
#pragma unroll
            for (int mi = 0; mi < 2; mi++)
#pragma unroll
                for (int ni = 0; ni < 4; ni++)
#pragma unroll
                    for (int j = 0; j < 4; j++) acc[g2][mi][ni][j] = 0.0f;

        const uint32_t amask = (uint32_t)((lid & 7) << 4);
        const uint32_t asel = (uint32_t)((lid >> 4) * 16);
        const uint32_t aRowOff = (uint32_t)(wid * 32 + (lid & 15)) * 128;
        const uint32_t bsel = (uint32_t)(((lid >> 3) & 1) * 16);
        const uint32_t bRow0 = (uint32_t)(((lid >> 4) << 3) + (lid & 7));

        for (int c = 0; c < NCH; c++) {
            const int st = c & 1;
            BAR_SYNC(BAR_FULL0 + st, 256);
            const uint32_t aHi = sb + (uint32_t)SM_A(st) + aRowOff;
            const uint32_t aLo = aHi + 16384;
            const uint32_t bHi = sb + (uint32_t)SM_B(st);
#pragma unroll
            for (int kk = 0; kk < 4; kk++) {
                const uint32_t ca = (asel + (uint32_t)(kk * 32)) ^ amask;
                const uint32_t cb = (bsel + (uint32_t)(kk * 32)) ^ amask;
                uint32_t ah[2][4], al[2][4];
#pragma unroll
                for (int mi = 0; mi < 2; mi++) {
                    ldmx4(ah[mi], aHi + (uint32_t)(mi * 2048) + ca);
                    ldmx4(al[mi], aLo + (uint32_t)(mi * 2048) + ca);
                }
#pragma unroll
                for (int g2 = 0; g2 < 2; g2++) {
                    const uint32_t bb = bHi + (uint32_t)(g2 * 32 * 128);
                    uint32_t bh[8], bl[8];
                    ldmx4(bh,     bb + bRow0 * 128 + cb);
                    ldmx4(bh + 4, bb + (bRow0 + 16) * 128 + cb);
                    ldmx4(bl,     bb + 8192 + bRow0 * 128 + cb);
                    ldmx4(bl + 4, bb + 8192 + (bRow0 + 16) * 128 + cb);
#pragma unroll
                    for (int mi = 0; mi < 2; mi++)
#pragma unroll
                        for (int ni = 0; ni < 4; ni++)
                            mma_bf16(acc[g2][mi][ni], ah[mi], bh[ni * 2], bh[ni * 2 + 1]);
#pragma unroll
                    for (int mi = 0; mi < 2; mi++)
#pragma unroll
                        for (int ni = 0; ni < 4; ni++)
                            mma_bf16(acc[g2][mi][ni], ah[mi], bl[ni * 2], bl[ni * 2 + 1]);
#pragma unroll
                    for (int mi = 0; mi < 2; mi++)
#pragma unroll
                        for (int ni = 0; ni < 4; ni++)
                            mma_bf16(acc[g2][mi][ni], al[mi], bh[ni * 2], bh[ni * 2 + 1]);
                }
            }
            BAR_ARRIVE(BAR_FREE0 + st, 256);
        }
        BAR_SYNC(BAR_CONS, 128);
        float* stg = reinterpret_cast<float*>(smem);
#pragma unroll
        for (int g2 = 0; g2 < 2; g2++)
#pragma unroll
            for (int mi = 0; mi < 2; mi++) {
                int row = wid * 32 + mi * 16 + (lid >> 2);
#pragma unroll
                for (int ni = 0; ni < 4; ni++) {
                    int col = g2 * 32 + ni * 8 + 2 * (lid & 3);
                    *reinterpret_cast<float2*>(&stg[row * STG + col]) =
                        make_float2(acc[g2][mi][ni][0], acc[g2][mi][ni][1]);
                    *reinterpret_cast<float2*>(&stg[(row + 8) * STG + col]) =
                        make_float2(acc[g2][mi][ni][2], acc[g2][mi][ni][3]);
                }
            }
        BAR_SYNC(BAR_STG, 256);
    }

    // ---- all 256 threads: coalesced write + fused 13-bit hist1 ----
    float* stg = reinterpret_cast<float*>(smem);
    const float* nz = noise + (size_t)rowBase * NEXP;
    float* op = out + (size_t)rowBase * NEXP;
#pragma unroll
    for (int j = 0; j < 8; j++) {
        int l = tid + j * 256;
        int r = l >> 4, q = (l & 15) * 4;
        float4 nv = *reinterpret_cast<const float4*>(nz + r * NEXP + q);
        float4 bv = *reinterpret_cast<const float4*>(bias + q);
        float4 o;
        o.x = (stg[r * STG + q + 0] + bv.x) + 0.1f * nv.x;
        o.y = (stg[r * STG + q + 1] + bv.y) + 0.1f * nv.y;
        o.z = (stg[r * STG + q + 2] + bv.z) + 0.1f * nv.z;
        o.w = (stg[r * STG + q + 3] + bv.w) + 0.1f * nv.w;
        *reinterpret_cast<float4*>(op + r * NEXP + q) = o;
        atomicAdd(&g_hist1[((q + 0) << 13) | (f2o(o.x) >> 19)], 1u);
        atomicAdd(&g_hist1[((q + 1) << 13) | (f2o(o.y) >> 19)], 1u);
        atomicAdd(&g_hist1[((q + 2) << 13) | (f2o(o.z) >> 19)], 1u);
        atomicAdd(&g_hist1[((q + 3) << 13) | (f2o(o.w) >> 19)], 1u);
    }
}

// ---------------- launch idx 2: find quantile buckets (64 CTAs) --------------
__global__ __launch_bounds__(256) void find_buckets() {
    __shared__ uint32_t sh[NBINS];
    __shared__ uint32_t wsum[8], woff[8];
    __shared__ uint32_t rbin, rrnk;
    const int tid = threadIdx.x, lane = tid & 31, w = tid >> 5;
    const int e = blockIdx.x;
    const uint32_t* h = &g_hist1[e << 13];
    for (int i = tid; i < NBINS; i += 256) sh[i] = h[i];
    __syncthreads();
    uint32_t bins[32];
    uint32_t s = 0;
#pragma unroll
    for (int j = 0; j < 32; j++) { bins[j] = sh[tid * 32 + j]; s += bins[j]; }
    uint32_t ps = warp_iscan(s, lane);
    if (lane == 31) wsum[w] = ps;
    __syncthreads();
    if (tid == 0) {
        uint32_t r2 = 0;
        for (int i = 0; i < 8; i++) { woff[i] = r2; r2 += wsum[i]; }
    }
    __syncthreads();
    uint32_t base = woff[w] + ps - s;
    if (base <= CRANK0 && CRANK0 < base + s) {
        uint32_t cum = base;
#pragma unroll
        for (int j = 0; j < 32; j++) {
            if (CRANK0 < cum + bins[j]) { rbin = (uint32_t)(tid * 32 + j); rrnk = CRANK0 - cum; break; }
            cum += bins[j];
        }
    }
    __syncthreads();
    if (tid == 0) {
        g_bkt0[e] = rbin; g_rnk0[e] = rrnk;
        g_blo[e] = o2f(rbin << 19);
        g_bhi[e] = o2f((rbin << 19) | 0x7FFFFu);
    }
}

// ---------------- launch idx 3 (profiled): pure streaming collect ------------
__global__ __launch_bounds__(256) void collect(const float4* __restrict__ lg, int n4) {
    const int tid = threadIdx.x;
    const int c0 = (tid * 4) & 63;
    uint32_t b0r[4];
    float lo[4], hi[4];
#pragma unroll
    for (int j = 0; j < 4; j++) {
        b0r[j] = g_bkt0[c0 + j];
        lo[j] = g_blo[c0 + j];
        hi[j] = g_bhi[c0 + j];
    }
    for (int i = blockIdx.x * 256 + tid; i < n4; i += gridDim.x * 256) {
        float4 v = lg[i];
        float vals[4] = {v.x, v.y, v.z, v.w};
#pragma unroll
        for (int j = 0; j < 4; j++) {
            float f = vals[j];
            if (f >= lo[j] && f <= hi[j]) {
                uint32_t u = f2o(f);               // exact confirm
                if ((u >> 19) == b0r[j]) {
                    uint32_t pos = atomicAdd(&g_cnt[c0 + j], 1u);
                    if (pos < CAP) g_cand[((c0 + j) << 13) | pos] = u;
                }
            }
        }
    }
}

// ---------------- launch idx 4: exact rank select (64 CTAs) ------------------
__global__ __launch_bounds__(256) void select_k() {
    __shared__ uint32_t hist[4096];
    __shared__ uint32_t wsum[8], woff[8];
    __shared__ uint32_t tb, bb;
    __shared__ uint32_t mbuf[64];
    __shared__ uint32_t mcnt;
    const int tid = threadIdx.x, lane = tid & 31, w = tid >> 5;
    const int e = blockIdx.x;
    const uint32_t* cand = &g_cand[e << 13];
    int n = (int)g_cnt[e]; if (n > CAP) n = CAP;
    const uint32_t r = g_rnk0[e];
#pragma unroll
    for (int j = 0; j < 16; j++) hist[tid * 16 + j] = 0u;
    __syncthreads();
    for (int i = tid; i < n; i += 256) atomicAdd(&hist[(cand[i] >> 7) & 0xFFFu], 1u);
    __syncthreads();
    uint32_t loc[16];
    uint32_t s = 0;
#pragma unroll
    for (int j = 0; j < 16; j++) { loc[j] = hist[tid * 16 + j]; s += loc[j]; }
    uint32_t ps = warp_iscan(s, lane);
    if (lane == 31) wsum[w] = ps;
    __syncthreads();
    if (tid == 0) {
        uint32_t r2 = 0;
        for (int i = 0; i < 8; i++) { woff[i] = r2; r2 += wsum[i]; }
        mcnt = 0u;
    }
    __syncthreads();
    uint32_t base = woff[w] + ps - s;
    if (base <= r && r < base + s) {
        uint32_t cum = base;
#pragma unroll
        for (int j = 0; j < 16; j++) {
            if (r < cum + loc[j]) { tb = (uint32_t)(tid * 16 + j); bb = cum; break; }
            cum += loc[j];
        }
    }
    __syncthreads();
    for (int i = tid; i < n; i += 256) {
        uint32_t u = cand[i];
        if (((u >> 7) & 0xFFFu) == tb) {
            uint32_t k = atomicAdd(&mcnt, 1u);
            if (k < 64) mbuf[k] = u;
        }
    }
    __syncthreads();
    if (tid == 0) {
        int m = (int)mcnt; if (m > 64) m = 64;
        for (int i2 = 1; i2 < m; i2++) {
            uint32_t key = mbuf[i2];
            int j2 = i2 - 1;
            while (j2 >= 0 && mbuf[j2] > key) { mbuf[j2 + 1] = mbuf[j2]; j2--; }
            mbuf[j2 + 1] = key;
        }
        g_tcol[e] = o2f(mbuf[r - bb]);    // t = s0 (exact mask)
    }
}

// ---------------- launch idx 5: row masks + softmax (smem-staged) ------------
__global__ __launch_bounds__(128) void row_pass(float* __restrict__ lg) {
    __shared__ __align__(16) float tc[NEXP];
    __shared__ __align__(16) float sdata[128 * 68];
    const int tid = threadIdx.x;
    if (tid < NEXP) tc[tid] = g_tcol[tid];

    const size_t base = (size_t)blockIdx.x * 128 * NEXP;
    const float4* in4 = reinterpret_cast<const float4*>(lg + base);
    float4* out4 = reinterpret_cast<float4*>(lg + base);

    // coalesced load -> padded smem (stride 68 floats)
#pragma unroll
    for (int j = 0; j < 16; j++) {
        int l = tid + j * 128;
        int r = l >> 4, q = l & 15;
        *reinterpret_cast<float4*>(&sdata[r * 68 + q * 4]) = in4[l];
    }
    __syncthreads();

    // per-thread scan of own row from smem
    const float4* t4 = reinterpret_cast<const float4*>(tc);
    float a = HIGH_NEG, b = HIGH_NEG, c = -3.402823466e38f;
    int ia = 0, ib = 0;
#define PROC(vv, tt, col) do {                                        \
        float m = (vv > tt) ? vv : HIGH_NEG;                          \
        bool ga = m > a, gb = m > b, gc = m > c;                      \
        float nc = gb ? b : (gc ? m : c);                             \
        int  nib = ga ? ia : (gb ? (col) : ib);                       \
        float nb = ga ? a : (gb ? m : b);                             \
        int  nia = ga ? (col) : ia;                                   \
        float na = ga ? m : a;                                        \
        a = na; b = nb; c = nc; ia = nia; ib = nib;                   \
    } while (0)
#pragma unroll
    for (int j = 0; j < 16; j++) {
        float4 v = *reinterpret_cast<const float4*>(&sdata[tid * 68 + j * 4]);
        float4 t = t4[j];
        PROC(v.x, t.x, j * 4 + 0);
        PROC(v.y, t.y, j * 4 + 1);
        PROC(v.z, t.z, j * 4 + 2);
        PROC(v.w, t.w, j * 4 + 3);
    }
#undef PROC

    // coalesced zero-fill of the whole block's output
    float4 z = make_float4(0.0f, 0.0f, 0.0f, 0.0f);
#pragma unroll
    for (int j = 0; j < 16; j++) out4[tid + j * 128] = z;
    __syncthreads();   // order zero-fill before patches

    float* op = lg + base + (size_t)tid * NEXP;
    if (a > c) {
        bool keepb = (b > c);
        float e1;
        asm("ex2.approx.f32 %0, %1;" : "=f"(e1) : "f"((b - a) * 1.4426950408889634f));
        e1 = keepb ? e1 : 0.0f;
        float inv;
        asm("rcp.approx.f32 %0, %1;" : "=f"(inv) : "f"(1.0f + e1));
        op[ia] = inv;
        if (keepb) op[ib] = e1 * inv;
    } else {
        float4 u = make_float4(0.015625f, 0.015625f, 0.015625f, 0.015625f);
        float4* opr = reinterpret_cast<float4*>(op);
#pragma unroll
        for (int j = 0; j < 16; j++) opr[j] = u;
    }
}

// ---------------- launch ----------------
extern "C" void kernel_launch(void* const* d_in, const int* in_sizes, int n_in,
                              void* d_out, int out_size) {
    const float *x = nullptr, *noise = nullptr, *W = nullptr, *bias = nullptr;
    for (int i = 0; i < n_in; i++) {
        switch (in_sizes[i]) {
            case NROWS * KDIM: x     = (const float*)d_in[i]; break;
            case NROWS * NEXP: noise = (const float*)d_in[i]; break;
            case NEXP * KDIM:  W     = (const float*)d_in[i]; break;
            case NEXP:         bias  = (const float*)d_in[i]; break;
            default: break;
        }
    }
    float* out = (float*)d_out;
    const int n4 = NROWS * NEXP / 4;

    cudaFuncSetAttribute(gemm_ws, cudaFuncAttributeMaxDynamicSharedMemorySize, SMEM_TOTAL);

    setup<<<512, 256>>>(W);                                          // idx 0
    gemm_ws<<<NROWS / BM, 256, SMEM_TOTAL>>>(x, bias, noise, out);   // idx 1
    find_buckets<<<NEXP, 256>>>();                                   // idx 2
    collect<<<2048, 256>>>((const float4*)out, n4);                  // idx 3 (profiled)
    select_k<<<NEXP, 256>>>();                                       // idx 4
    row_pass<<<NROWS / 128, 128>>>(out);                             // idx 5
}